// round 5
// baseline (speedup 1.0000x reference)
#include <cuda_runtime.h>
#include <cuda_fp16.h>
#include <math.h>
#include <stdint.h>

// Problem dims
#define B_  4
#define S_  1024
#define D_  1024
#define H_  512
#define N_  32
#define M_  (B_ * S_)    // 4096
#define H2_ (2 * H_)     // 1024

typedef unsigned long long u64;

// ---------------------------------------------------------------------------
// Scratch (__device__ globals; no allocs allowed)
// ---------------------------------------------------------------------------
__device__ __half g_qh[M_ * D_],  g_ql[M_ * D_];    // query split hi/lo fp16
__device__ __half g_hh[M_ * H2_], g_hl[M_ * H2_];   // GELU(h) split hi/lo fp16
__device__ __half g_w1f[D_ * H2_];                  // W1 fp16 (single)
__device__ __half g_w2f[H2_ * H_];                  // W2 fp16 (single)
__device__ float g_c[B_ * N_ * H_];

// ---------------------------------------------------------------------------
// PTX helpers
// ---------------------------------------------------------------------------
__device__ __forceinline__ uint32_t smem_u32(const void* p) {
    uint32_t a;
    asm("{ .reg .u64 t; cvta.to.shared.u64 t, %1; cvt.u32.u64 %0, t; }" : "=r"(a) : "l"(p));
    return a;
}
__device__ __forceinline__ void ldsm_x4(uint32_t& r0, uint32_t& r1, uint32_t& r2, uint32_t& r3,
                                        uint32_t addr) {
    asm volatile("ldmatrix.sync.aligned.m8n8.x4.shared.b16 {%0,%1,%2,%3}, [%4];"
                 : "=r"(r0), "=r"(r1), "=r"(r2), "=r"(r3) : "r"(addr));
}
__device__ __forceinline__ void ldsm_x4t(uint32_t& r0, uint32_t& r1, uint32_t& r2, uint32_t& r3,
                                         uint32_t addr) {
    asm volatile("ldmatrix.sync.aligned.m8n8.x4.trans.shared.b16 {%0,%1,%2,%3}, [%4];"
                 : "=r"(r0), "=r"(r1), "=r"(r2), "=r"(r3) : "r"(addr));
}
__device__ __forceinline__ void mma_f16(float* d, uint32_t a0, uint32_t a1, uint32_t a2,
                                        uint32_t a3, uint32_t b0, uint32_t b1) {
    asm volatile(
        "mma.sync.aligned.m16n8k16.row.col.f32.f16.f16.f32 "
        "{%0,%1,%2,%3}, {%4,%5,%6,%7}, {%8,%9}, {%0,%1,%2,%3};"
        : "+f"(d[0]), "+f"(d[1]), "+f"(d[2]), "+f"(d[3])
        : "r"(a0), "r"(a1), "r"(a2), "r"(a3), "r"(b0), "r"(b1));
}
__device__ __forceinline__ void cp16(uint32_t smem_addr, const void* gptr) {
    asm volatile("cp.async.cg.shared.global [%0], [%1], 16;" :: "r"(smem_addr), "l"(gptr));
}
#define CP_COMMIT() asm volatile("cp.async.commit_group;" ::: "memory")
#define CP_WAIT2()  asm volatile("cp.async.wait_group 2;" ::: "memory")
#define CP_WAIT1()  asm volatile("cp.async.wait_group 1;" ::: "memory")
#define CP_WAIT0()  asm volatile("cp.async.wait_group 0;" ::: "memory")

// Packed fp32x2 FMA (Blackwell FFMA2)
__device__ __forceinline__ u64 f2fma(u64 d, u64 a, u64 b) {
    asm("fma.rn.f32x2 %0, %1, %2, %0;" : "+l"(d) : "l"(a), "l"(b));
    return d;
}
__device__ __forceinline__ u64 dup2(float x) {
    u64 r;
    asm("mov.b64 %0, {%1, %1};" : "=l"(r) : "f"(x));
    return r;
}
__device__ __forceinline__ void unpack2(u64 v, float& lo, float& hi) {
    asm("mov.b64 {%0, %1}, %2;" : "=f"(lo), "=f"(hi) : "l"(v));
}

// ---------------------------------------------------------------------------
// Prep: fp32 -> fp16 hi/lo split, and fp32 -> fp16 single
// ---------------------------------------------------------------------------
__global__ void split_half(const float* __restrict__ src,
                           __half* __restrict__ dh, __half* __restrict__ dl, int n4) {
    int i = blockIdx.x * blockDim.x + threadIdx.x;
    if (i >= n4) return;
    float4 v = ((const float4*)src)[i];
    float vv[4] = {v.x, v.y, v.z, v.w};
    uint32_t hh[4], ll[4];
#pragma unroll
    for (int q = 0; q < 4; q++) {
        __half h = __float2half_rn(vv[q]);
        __half l = __float2half_rn(vv[q] - __half2float(h));
        hh[q] = __half_as_ushort(h);
        ll[q] = __half_as_ushort(l);
    }
    uint2 ph, pl;
    ph.x = hh[0] | (hh[1] << 16); ph.y = hh[2] | (hh[3] << 16);
    pl.x = ll[0] | (ll[1] << 16); pl.y = ll[2] | (ll[3] << 16);
    ((uint2*)dh)[i] = ph;
    ((uint2*)dl)[i] = pl;
}

__global__ void conv_half(const float* __restrict__ src, __half* __restrict__ d, int n4) {
    int i = blockIdx.x * blockDim.x + threadIdx.x;
    if (i >= n4) return;
    float4 v = ((const float4*)src)[i];
    float vv[4] = {v.x, v.y, v.z, v.w};
    uint32_t hh[4];
#pragma unroll
    for (int q = 0; q < 4; q++) hh[q] = __half_as_ushort(__float2half_rn(vv[q]));
    uint2 ph;
    ph.x = hh[0] | (hh[1] << 16); ph.y = hh[2] | (hh[3] << 16);
    ((uint2*)d)[i] = ph;
}

// ---------------------------------------------------------------------------
// Tensor-core GEMM (mma.sync fp16, 2-term A-split): C = (Ah+Al) @ Bf + bias
//   Ah/Al: fp16 [Mtot, K] row-major.  Bf: fp16 [K, Ntot] row-major.
// Tile 128x128, BK=64, 8 warps (2x4 -> warp tile 64x32), 3-stage cp.async.
// MODE 0: GELU(acc+bias) -> split fp16 (outH/outL).  MODE 1: acc+bias -> fp32.
// stage (48KB): Ah[128][64] +0 | Al +16K | Bf[64][128] +32K ; stride 48K, 3 stages.
// swizzle: 16B-unit u at row r -> A: u^(r&7); B: (u&8)|((u^r)&7)
// ---------------------------------------------------------------------------
template <int MODE>
__global__ void __launch_bounds__(256, 1)
gemm_mma(const __half* __restrict__ Ah, const __half* __restrict__ Al,
         const __half* __restrict__ Bf,
         const float* __restrict__ bias,
         float* __restrict__ outF,
         __half* __restrict__ outH, __half* __restrict__ outL,
         int Ntot, int Ktot) {
    extern __shared__ char smp[];
    const uint32_t sb = smem_u32(smp);
    const int tid = threadIdx.x;
    const int wid = tid >> 5, lane = tid & 31;
    const int wm = wid >> 2, wn = wid & 3;
    const int m_warp = wm * 64, n_warp = wn * 32;
    const int m0 = blockIdx.y * 128, n0 = blockIdx.x * 128;
    const int gid = lane >> 2, tig = lane & 3;
    const uint32_t STG = 49152;

    auto load_stage = [&](int c, int buf) {
        const uint32_t bb = sb + (uint32_t)buf * STG;
        const int k0 = c * 64;
#pragma unroll
        for (int j = 0; j < 4; j++) {          // A: 128 rows x 8 units, hi+lo
            int g = tid + 256 * j;
            int r = g >> 3, u = g & 7;
            size_t so = (size_t)(m0 + r) * Ktot + k0 + u * 8;
            uint32_t sw = (uint32_t)(r * 128 + ((u ^ (r & 7)) << 4));
            cp16(bb + sw, Ah + so);
            cp16(bb + 16384 + sw, Al + so);
        }
#pragma unroll
        for (int j = 0; j < 4; j++) {          // B: 64 rows x 16 units (single)
            int g = tid + 256 * j;
            int r = g >> 4, u = g & 15;
            size_t so = (size_t)(k0 + r) * Ntot + n0 + u * 8;
            uint32_t sw = (uint32_t)(r * 256 + (((u & 8) | ((u ^ r) & 7)) << 4));
            cp16(bb + 32768 + sw, Bf + so);
        }
    };

    float acc[4][4][4] = {};
    const int NK = Ktot / 64;

    load_stage(0, 0); CP_COMMIT();
    load_stage(1, 1); CP_COMMIT();

    for (int c = 0; c < NK; c++) {
        if (c + 2 < NK) { load_stage(c + 2, (c + 2) % 3); CP_COMMIT(); }
        if (c + 2 < NK)      CP_WAIT2();
        else if (c + 1 < NK) CP_WAIT1();
        else                 CP_WAIT0();
        __syncthreads();

        const uint32_t bb = sb + (uint32_t)(c % 3) * STG;
#pragma unroll
        for (int s = 0; s < 4; s++) {
            uint32_t bfr[2][4];
            {
                const int kr = s * 16 + (lane & 7) + (lane & 8);
                const uint32_t swk = (uint32_t)(kr * 256);
#pragma unroll
                for (int nt = 0; nt < 2; nt++) {
                    int un = (n_warp >> 3) + nt * 2 + (lane >> 4);
                    uint32_t sw = swk + (uint32_t)((((un & 8) | ((un ^ kr) & 7)) << 4));
                    ldsm_x4t(bfr[nt][0], bfr[nt][1], bfr[nt][2], bfr[nt][3], bb + 32768 + sw);
                }
            }
            const int ar = m_warp + (lane & 15);
            const int au = s * 2 + (lane >> 4);
#pragma unroll
            for (int mt = 0; mt < 4; mt++) {
                const int r = ar + mt * 16;
                uint32_t sw = (uint32_t)(r * 128 + ((au ^ (r & 7)) << 4));
                uint32_t ah0, ah1, ah2, ah3, al0, al1, al2, al3;
                ldsm_x4(ah0, ah1, ah2, ah3, bb + sw);
                ldsm_x4(al0, al1, al2, al3, bb + 16384 + sw);
#pragma unroll
                for (int nb = 0; nb < 4; nb++) {
                    const int nt = nb >> 1, hf = (nb & 1) * 2;
                    mma_f16(acc[mt][nb], ah0, ah1, ah2, ah3, bfr[nt][hf], bfr[nt][hf + 1]);
                    mma_f16(acc[mt][nb], al0, al1, al2, al3, bfr[nt][hf], bfr[nt][hf + 1]);
                }
            }
        }
        __syncthreads();
    }

    // ---- epilogue ----
#pragma unroll
    for (int mt = 0; mt < 4; mt++) {
        const int r0 = m0 + m_warp + mt * 16 + gid;
#pragma unroll
        for (int j = 0; j < 4; j++) {
            const int col = n0 + n_warp + j * 8 + tig * 2;
            float2 bv = *(const float2*)&bias[col];
            float v[4];
            v[0] = acc[mt][j][0] + bv.x; v[1] = acc[mt][j][1] + bv.y;
            v[2] = acc[mt][j][2] + bv.x; v[3] = acc[mt][j][3] + bv.y;
            if (MODE == 0) {
#pragma unroll
                for (int q = 0; q < 4; q++)
                    v[q] = 0.5f * v[q] * (1.0f + erff(v[q] * 0.70710678118654752f));
#pragma unroll
                for (int hp = 0; hp < 2; hp++) {
                    const int rr = r0 + hp * 8;
                    float a = v[hp * 2], b = v[hp * 2 + 1];
                    __half h0 = __float2half_rn(a);
                    __half h1 = __float2half_rn(b);
                    __half l0 = __float2half_rn(a - __half2float(h0));
                    __half l1 = __float2half_rn(b - __half2float(h1));
                    uint32_t ph = (uint32_t)__half_as_ushort(h0) | ((uint32_t)__half_as_ushort(h1) << 16);
                    uint32_t pl = (uint32_t)__half_as_ushort(l0) | ((uint32_t)__half_as_ushort(l1) << 16);
                    *(uint32_t*)(outH + (size_t)rr * Ntot + col) = ph;
                    *(uint32_t*)(outL + (size_t)rr * Ntot + col) = pl;
                }
            } else {
                *(float2*)(outF + (size_t)r0 * Ntot + col) = make_float2(v[0], v[1]);
                *(float2*)(outF + (size_t)(r0 + 8) * Ntot + col) = make_float2(v[2], v[3]);
            }
        }
    }
}

// ---------------------------------------------------------------------------
// Row-wise L2 normalize in place
// ---------------------------------------------------------------------------
__global__ void normalize_rows(float* __restrict__ keys) {
    const int row = blockIdx.x;
    const int t = threadIdx.x;
    float4* p = (float4*)(keys + (size_t)row * H_);
    float4 v = p[t];
    float ss = v.x * v.x + v.y * v.y + v.z * v.z + v.w * v.w;
#pragma unroll
    for (int o = 16; o; o >>= 1) ss += __shfl_xor_sync(0xffffffffu, ss, o);
    __shared__ float ws[4];
    if ((t & 31) == 0) ws[t >> 5] = ss;
    __syncthreads();
    float tot = ws[0] + ws[1] + ws[2] + ws[3];
    float inv = 1.0f / fmaxf(sqrtf(tot), 1e-12f);
    v.x *= inv; v.y *= inv; v.z *= inv; v.w *= inv;
    p[t] = v;
}

// ---------------------------------------------------------------------------
// c[b,n,i] = sum_j hcm[b,n,(i+j)%H] * Wa[j]
// ---------------------------------------------------------------------------
__global__ void compute_c_kernel(const float* __restrict__ hcm,
                                 const float* __restrict__ Wa,
                                 float* __restrict__ c) {
    __shared__ __align__(16) float hs[1024];
    __shared__ __align__(16) float was[512];
    const int bn = blockIdx.x;
    const int t = threadIdx.x;
#pragma unroll
    for (int r = 0; r < 4; r++) {
        int j = t + 128 * r;
        float v = hcm[(size_t)bn * H_ + j];
        hs[j] = v; hs[j + 512] = v;
        was[j] = Wa[j];
    }
    __syncthreads();
    const int h0 = 4 * t;
    float4 a = {0.f, 0.f, 0.f, 0.f};
    float4 mw = *(const float4*)&hs[h0];
#pragma unroll 4
    for (int i = 0; i < 512; i += 4) {
        float4 kv = *(const float4*)&was[i];
        float4 mn = *(const float4*)&hs[i + 4 + h0];
        a.x = fmaf(kv.x, mw.x, a.x); a.y = fmaf(kv.x, mw.y, a.y); a.z = fmaf(kv.x, mw.z, a.z); a.w = fmaf(kv.x, mw.w, a.w);
        a.x = fmaf(kv.y, mw.y, a.x); a.y = fmaf(kv.y, mw.z, a.y); a.z = fmaf(kv.y, mw.w, a.z); a.w = fmaf(kv.y, mn.x, a.w);
        a.x = fmaf(kv.z, mw.z, a.x); a.y = fmaf(kv.z, mw.w, a.y); a.z = fmaf(kv.z, mn.x, a.z); a.w = fmaf(kv.z, mn.y, a.w);
        a.x = fmaf(kv.w, mw.w, a.x); a.y = fmaf(kv.w, mn.x, a.y); a.z = fmaf(kv.w, mn.y, a.z); a.w = fmaf(kv.w, mn.z, a.w);
        mw = mn;
    }
    *(float4*)&c[(size_t)bn * H_ + h0] = a;
}

// ---------------------------------------------------------------------------
// Fused slot attention per (b,s) row — f32x2 (FFMA2) lane-split correlation.
//   k2[i]  = (k[i], k[i+256])               i in [0,256)
//   mm2[x] = (m[x mod 512], m[(x+256) mod 512])   x in [0,768)
//   out[h] = lanesum( sum_{i<256} k2[i] .* mm2[i+h] )
// ---------------------------------------------------------------------------
__global__ __launch_bounds__(128)
void attention_kernel(const float* __restrict__ keys,
                      const float* __restrict__ c,
                      const float* __restrict__ hcm,
                      const float* __restrict__ ba,
                      float* __restrict__ context) {
    __shared__ __align__(16) float ks[512];
    __shared__ __align__(16) float k2f[512];     // 256 float2
    __shared__ __align__(16) float mmf[1536];    // 768 float2
    __shared__ float sc[32];
    __shared__ float wt[32];

    const int row = blockIdx.x;
    const int b = row >> 10;
    const int t = threadIdx.x;

    // load keys row; build ks and k2
    {
        float4 kv = ((const float4*)(keys + (size_t)row * H_))[t];
        ((float4*)ks)[t] = kv;
        float vv[4] = {kv.x, kv.y, kv.z, kv.w};
        const int j = 4 * t;
#pragma unroll
        for (int q = 0; q < 4; q++) {
            int i = j + q;
            if (i < 256) k2f[2 * i] = vv[q];           // k2[i].x
            else         k2f[2 * (i - 256) + 1] = vv[q]; // k2[i-256].y
        }
    }
    __syncthreads();

    // scores: 32 slots x 4 lanes each
    {
        const int n = t >> 2, l = t & 3;
        const float4* c4 = (const float4*)(c + ((size_t)(b * N_ + n)) * H_);
        const float4* k4 = (const float4*)ks;
        float p = 0.f;
#pragma unroll 4
        for (int i = l; i < 128; i += 4) {
            float4 cv = c4[i], kv = k4[i];
            p += cv.x * kv.x + cv.y * kv.y + cv.z * kv.z + cv.w * kv.w;
        }
        p += __shfl_xor_sync(0xffffffffu, p, 1);
        p += __shfl_xor_sync(0xffffffffu, p, 2);
        if (l == 0) sc[n] = p + ba[0];
    }
    __syncthreads();

    // softmax over 32 slots in warp 0
    if (t < 32) {
        float v = sc[t];
        float mx = v;
#pragma unroll
        for (int o = 16; o; o >>= 1) mx = fmaxf(mx, __shfl_xor_sync(0xffffffffu, mx, o));
        float e = expf(v - mx);
        float sm = e;
#pragma unroll
        for (int o = 16; o; o >>= 1) sm += __shfl_xor_sync(0xffffffffu, sm, o);
        wt[t] = e / sm;
    }
    __syncthreads();

    // mixture: m[4t..4t+3] = sum_n wt[n]*hcm[b,n,4t..4t+3]; scatter into mm2
    {
        u64 a01 = 0, a23 = 0;
        const char* hb = (const char*)(hcm + ((size_t)b * N_) * H_ + 4 * t);
#pragma unroll 8
        for (int n = 0; n < 32; n++) {
            ulonglong2 hv = *(const ulonglong2*)(hb + (size_t)n * H_ * 4);
            u64 w2 = dup2(wt[n]);
            a01 = f2fma(a01, w2, hv.x);
            a23 = f2fma(a23, w2, hv.y);
        }
        float mv[4];
        unpack2(a01, mv[0], mv[1]);
        unpack2(a23, mv[2], mv[3]);
        const int j = 4 * t;
#pragma unroll
        for (int q = 0; q < 4; q++) {
            int jq = j + q;
            float m = mv[q];
            mmf[2 * jq] = m;               // mm2[jq].x
            mmf[2 * (jq + 256) + 1] = m;   // mm2[jq+256].y
            if (jq < 256) mmf[2 * (jq + 512)] = m;      // mm2[jq+512].x
            else          mmf[2 * (jq - 256) + 1] = m;  // mm2[jq-256].y
        }
    }
    __syncthreads();

    // correlation: 4 outputs per thread, lane-split over i-halves, f32x2 FMAs
    {
        const int h0 = 4 * t;
        const u64* k2p = (const u64*)k2f;
        const u64* mmp = (const u64*)mmf;
        u64 A0 = 0, A1 = 0, A2 = 0, A3 = 0;
        u64 w0 = mmp[h0], w1 = mmp[h0 + 1], w2 = mmp[h0 + 2], w3 = mmp[h0 + 3];
#pragma unroll 4
        for (int i = 0; i < 256; i += 4) {
            ulonglong2 ka = *(const ulonglong2*)&k2p[i];
            ulonglong2 kb = *(const ulonglong2*)&k2p[i + 2];
            ulonglong2 wa = *(const ulonglong2*)&mmp[i + h0 + 4];
            ulonglong2 wb = *(const ulonglong2*)&mmp[i + h0 + 6];
            A0 = f2fma(A0, ka.x, w0); A1 = f2fma(A1, ka.x, w1); A2 = f2fma(A2, ka.x, w2); A3 = f2fma(A3, ka.x, w3);
            A0 = f2fma(A0, ka.y, w1); A1 = f2fma(A1, ka.y, w2); A2 = f2fma(A2, ka.y, w3); A3 = f2fma(A3, ka.y, wa.x);
            A0 = f2fma(A0, kb.x, w2); A1 = f2fma(A1, kb.x, w3); A2 = f2fma(A2, kb.x, wa.x); A3 = f2fma(A3, kb.x, wa.y);
            A0 = f2fma(A0, kb.y, w3); A1 = f2fma(A1, kb.y, wa.x); A2 = f2fma(A2, kb.y, wa.y); A3 = f2fma(A3, kb.y, wb.x);
            w0 = wa.x; w1 = wa.y; w2 = wb.x; w3 = wb.y;
        }
        float x0, y0, x1, y1, x2, y2, x3, y3;
        unpack2(A0, x0, y0); unpack2(A1, x1, y1);
        unpack2(A2, x2, y2); unpack2(A3, x3, y3);
        float4 r = make_float4(x0 + y0, x1 + y1, x2 + y2, x3 + y3);
        *(float4*)(context + (size_t)row * H_ + h0) = r;
    }
}

// ---------------------------------------------------------------------------
// Launch
// ---------------------------------------------------------------------------
extern "C" void kernel_launch(void* const* d_in, const int* in_sizes, int n_in,
                              void* d_out, int out_size) {
    const float* query = (const float*)d_in[0];
    const float* hcm   = (const float*)d_in[1];
    const float* W1    = (const float*)d_in[2];
    const float* b1    = (const float*)d_in[3];
    const float* W2    = (const float*)d_in[4];
    const float* b2    = (const float*)d_in[5];
    const float* Wa    = (const float*)d_in[6];
    const float* ba    = (const float*)d_in[7];

    float* out = (float*)d_out;
    float* context = out;
    float* keys    = out + (size_t)M_ * H_;

    __half *qh, *ql, *hh, *hl, *w1f, *w2f;
    float* cbuf;
    cudaGetSymbolAddress((void**)&qh, g_qh);
    cudaGetSymbolAddress((void**)&ql, g_ql);
    cudaGetSymbolAddress((void**)&hh, g_hh);
    cudaGetSymbolAddress((void**)&hl, g_hl);
    cudaGetSymbolAddress((void**)&w1f, g_w1f);
    cudaGetSymbolAddress((void**)&w2f, g_w2f);
    cudaGetSymbolAddress((void**)&cbuf, g_c);

    const int SMEM_BYTES = 3 * 49152;   // 147456
    cudaFuncSetAttribute(gemm_mma<0>, cudaFuncAttributeMaxDynamicSharedMemorySize, SMEM_BYTES);
    cudaFuncSetAttribute(gemm_mma<1>, cudaFuncAttributeMaxDynamicSharedMemorySize, SMEM_BYTES);

    // prep
    split_half<<<(M_ * D_ / 4 + 255) / 256, 256>>>(query, qh, ql, M_ * D_ / 4);
    conv_half<<<(D_ * H2_ / 4 + 255) / 256, 256>>>(W1, w1f, D_ * H2_ / 4);
    conv_half<<<(H2_ * H_ / 4 + 255) / 256, 256>>>(W2, w2f, H2_ * H_ / 4);
    compute_c_kernel<<<B_ * N_, 128>>>(hcm, Wa, cbuf);

    // GEMM1: h = GELU(query@W1+b1) -> split fp16
    gemm_mma<0><<<dim3(H2_ / 128, M_ / 128), 256, SMEM_BYTES>>>(
        qh, ql, w1f, b1, nullptr, hh, hl, H2_, D_);
    // GEMM2: keys = h@W2+b2 (fp32)
    gemm_mma<1><<<dim3(H_ / 128, M_ / 128), 256, SMEM_BYTES>>>(
        hh, hl, w2f, b2, keys, nullptr, nullptr, H_, H2_);

    normalize_rows<<<M_, 128>>>(keys);
    attention_kernel<<<M_, 128>>>(keys, cbuf, hcm, ba, context);
}